// round 7
// baseline (speedup 1.0000x reference)
#include <cuda_runtime.h>

#define NN 8
#define CC 19
#define HW (512*512)
#define HW4 (HW/4)
#define TPB 256
#define NWARP (TPB/32)
#define NBLK (HW4/TPB)        // 256 blocks per image in x

// ---- persistent device scratch (zero-initialized at load; self-reset each call) ----
__device__ int    g_hseg[NN][CC], g_hatt[NN][CC];
__device__ int    g_pos, g_neg;
__device__ double g_bce_pos, g_bce_neg;
__device__ double g_seg_num[NN], g_seg_den[NN], g_att_num[NN], g_att_den[NN];
__device__ float  g_wseg[NN][CC], g_watt[NN][CC];
__device__ unsigned g_done, g_hdone;
__device__ unsigned char g_pk[NN * HW];   // 2 MB packed: class(5b) | att<<5

// block-reduce 4 floats (NWARP warps); result valid on (warp0, lane0)
__device__ __forceinline__ void block_reduce4(float& v0, float& v1, float& v2, float& v3,
                                              float (*red)[4]) {
    #pragma unroll
    for (int off = 16; off; off >>= 1) {
        v0 += __shfl_down_sync(0xffffffffu, v0, off);
        v1 += __shfl_down_sync(0xffffffffu, v1, off);
        v2 += __shfl_down_sync(0xffffffffu, v2, off);
        v3 += __shfl_down_sync(0xffffffffu, v3, off);
    }
    const int lane = threadIdx.x & 31, wrp = threadIdx.x >> 5;
    if (lane == 0) { red[wrp][0]=v0; red[wrp][1]=v1; red[wrp][2]=v2; red[wrp][3]=v3; }
    __syncthreads();
    if (wrp == 0) {
        v0 = (lane < NWARP) ? red[lane][0] : 0.f;
        v1 = (lane < NWARP) ? red[lane][1] : 0.f;
        v2 = (lane < NWARP) ? red[lane][2] : 0.f;
        v3 = (lane < NWARP) ? red[lane][3] : 0.f;
        #pragma unroll
        for (int off = 4; off; off >>= 1) {
            v0 += __shfl_down_sync(0xffffffffu, v0, off);
            v1 += __shfl_down_sync(0xffffffffu, v1, off);
            v2 += __shfl_down_sync(0xffffffffu, v2, off);
            v3 += __shfl_down_sync(0xffffffffu, v3, off);
        }
    }
}

// Pass 1: hist + BCE partials + packed class/att bytes. Last finishing block
// converts histograms into final per-image per-class weights.
__global__ void __launch_bounds__(TPB) k_hist(const int*   __restrict__ segmask,
                                              const float* __restrict__ edgein,
                                              const int*   __restrict__ edgemask) {
    const int n   = blockIdx.y;
    const int tid = threadIdx.x;
    const int wrp = tid >> 5;

    __shared__ int   shseg[NWARP][CC], shatt[NWARP][CC];
    __shared__ float red[NWARP][4];
    for (int j = tid; j < NWARP*CC; j += TPB) { ((int*)shseg)[j] = 0; ((int*)shatt)[j] = 0; }
    __syncthreads();

    const int i = n * HW4 + blockIdx.x * TPB + tid;
    const int4   t4 = ((const int4*  )segmask )[i];
    const float4 e4 = ((const float4*)edgein  )[i];
    const int4   m4 = ((const int4*  )edgemask)[i];

    float bp = 0.f, bn = 0.f; int cp = 0, cn = 0;
    uchar4 pk;
    #define P1(tj, ej, mj, pkj)                                            \
    {                                                                      \
        const bool att = (ej) > 0.8f;                                      \
        if ((unsigned)(tj) < CC) {                                         \
            atomicAdd(&shseg[wrp][tj], 1);                                 \
            if (att) atomicAdd(&shatt[wrp][tj], 1);                        \
            pkj = (unsigned char)((tj) | (att ? 32 : 0));                  \
        } else pkj = 31;                                                   \
        const float bce = fmaxf(ej, 0.f) - (ej) * (float)(mj)              \
                        + log1pf(__expf(-fabsf(ej)));                      \
        if ((mj) == 1)      { bp += bce; cp++; }                           \
        else if ((mj) == 0) { bn += bce; cn++; }                           \
    }
    P1(t4.x, e4.x, m4.x, pk.x)
    P1(t4.y, e4.y, m4.y, pk.y)
    P1(t4.z, e4.z, m4.z, pk.z)
    P1(t4.w, e4.w, m4.w, pk.w)
    #undef P1
    ((uchar4*)g_pk)[i] = pk;

    float v0 = bp, v1 = bn, v2 = (float)cp, v3 = (float)cn;
    __syncthreads();
    block_reduce4(v0, v1, v2, v3, red);
    if (tid == 0) {
        atomicAdd(&g_bce_pos, (double)v0);
        atomicAdd(&g_bce_neg, (double)v1);
        atomicAdd(&g_pos, (int)v2);
        atomicAdd(&g_neg, (int)v3);
    }
    __syncthreads();
    if (tid < CC) {
        int s = 0, a = 0;
        #pragma unroll
        for (int w = 0; w < NWARP; w++) { s += shseg[w][tid]; a += shatt[w][tid]; }
        if (s) atomicAdd(&g_hseg[n][tid], s);
        if (a) atomicAdd(&g_hatt[n][tid], a);
    }

    // ---- last finishing block turns histograms into final weights ----
    __shared__ bool s_last;
    __shared__ float tot_s[NN], tot_a[NN];
    __syncthreads();
    if (tid == 0) {
        __threadfence();
        s_last = (atomicAdd(&g_hdone, 1u) == (unsigned)(NN * NBLK) - 1u);
    }
    __syncthreads();
    if (s_last) {
        if (tid < NN) {
            int s = 0, a = 0;
            #pragma unroll
            for (int c = 0; c < CC; c++) { s += g_hseg[tid][c]; a += g_hatt[tid][c]; }
            tot_s[tid] = fmaxf((float)s, 1.0f);
            tot_a[tid] = fmaxf((float)a, 1.0f);
        }
        __syncthreads();
        if (tid < NN*CC) {
            const int nn = tid / CC, c = tid % CC;
            const int cs = g_hseg[nn][c], ca = g_hatt[nn][c];
            g_wseg[nn][c] = (cs > 0 ? (1.0f - (float)cs / tot_s[nn]) : 0.0f) + 1.0f;
            g_watt[nn][c] = (ca > 0 ? (1.0f - (float)ca / tot_a[nn]) : 0.0f) + 1.0f;
        }
    }
}

// Pass 2: segin (159.4MB) + pk (2.1MB). Weights precomputed -> trivial prologue.
__global__ void __launch_bounds__(TPB) k_main(const float* __restrict__ segin,
                                              float* __restrict__ out) {
    const int n   = blockIdx.y;
    const int tid = threadIdx.x;

    __shared__ float swseg[CC], swatt[CC];
    __shared__ float red[NWARP][4];

    // issue the pk load first so it overlaps the tiny weight prologue
    const int p = blockIdx.x * TPB + tid;          // float4 index in [0,HW4)
    const uchar4 pk4 = ((const uchar4*)g_pk)[n * HW4 + p];

    if (tid < CC) {
        swseg[tid] = g_wseg[n][tid];
        swatt[tid] = g_watt[n][tid];
    }
    __syncthreads();

    const int pk[4] = { pk4.x, pk4.y, pk4.z, pk4.w };

    float se[4] = {0.f, 0.f, 0.f, 0.f};
    float xt[4] = {0.f, 0.f, 0.f, 0.f};
    const float4* base = (const float4*)(segin + (size_t)n * CC * HW) + p;
    #pragma unroll
    for (int c = 0; c < CC; c++) {
        const float4 v = __ldcs(&base[(size_t)c * HW4]);   // streaming: no reuse
        se[0] += __expf(v.x); if ((pk[0] & 31) == c) xt[0] = v.x;
        se[1] += __expf(v.y); if ((pk[1] & 31) == c) xt[1] = v.y;
        se[2] += __expf(v.z); if ((pk[2] & 31) == c) xt[2] = v.z;
        se[3] += __expf(v.w); if ((pk[3] & 31) == c) xt[3] = v.w;
    }

    float seg_num = 0.f, seg_den = 0.f, att_num = 0.f, att_den = 0.f;
    #pragma unroll
    for (int j = 0; j < 4; j++) {
        const int tc = pk[j] & 31;
        if (tc < CC) {
            const float nlp = __logf(se[j]) - xt[j];
            const float w = swseg[tc];
            seg_num += w * nlp;
            seg_den += w;
            if (pk[j] & 32) {
                const float wa = swatt[tc];
                att_num += wa * nlp;
                att_den += wa;
            }
        }
    }
    __syncthreads();
    block_reduce4(seg_num, seg_den, att_num, att_den, red);

    // epilogue: flush partials; last finishing block computes outputs + resets scratch.
    if (tid < 32) {
        bool last = false;
        if (tid == 0) {
            atomicAdd(&g_seg_num[n], (double)seg_num);
            atomicAdd(&g_seg_den[n], (double)seg_den);
            atomicAdd(&g_att_num[n], (double)att_num);
            atomicAdd(&g_att_den[n], (double)att_den);
            __threadfence();
            last = (atomicAdd(&g_done, 1u) == (unsigned)(NN * NBLK) - 1u);
        }
        if (__shfl_sync(0xffffffffu, last ? 1 : 0, 0)) {
            // parallel loads across lanes (everything is L2-hot)
            double contrib = 0.0;
            if (tid < NN) {
                contrib = g_seg_num[tid] / fmax(g_seg_den[tid], 1e-12);
            } else if (tid < 2*NN) {
                contrib = g_att_num[tid - NN] / fmax(g_att_den[tid - NN], 1e-12);
            }
            double seg = (tid < NN)  ? contrib : 0.0;
            double att = (tid >= NN && tid < 2*NN) ? contrib : 0.0;
            #pragma unroll
            for (int off = 16; off; off >>= 1) {
                seg += __shfl_down_sync(0xffffffffu, seg, off);
                att += __shfl_down_sync(0xffffffffu, att, off);
            }
            if (tid == 0) {
                const double p_ = (double)g_pos, q_ = (double)g_neg;
                const double s_ = fmax(p_ + q_, 1.0);
                const double bce = (q_ / s_) * g_bce_pos + (p_ / s_) * g_bce_neg;
                out[0] = (float)seg;
                out[1] = (float)(20.0 * bce / (double)((long long)NN * HW));
                out[2] = (float)att;
                out[3] = 0.0f;
            }
            __syncwarp();
            // reset ALL scratch for the next call (no other blocks are running)
            for (int j = tid; j < NN*CC; j += 32) {
                ((int*)g_hseg)[j] = 0;
                ((int*)g_hatt)[j] = 0;
            }
            if (tid < NN) {
                g_seg_num[tid] = 0.0; g_seg_den[tid] = 0.0;
                g_att_num[tid] = 0.0; g_att_den[tid] = 0.0;
            }
            if (tid == 0) {
                g_bce_pos = 0.0; g_bce_neg = 0.0;
                g_pos = 0; g_neg = 0;
                g_done = 0u; g_hdone = 0u;
            }
        }
    }
}

extern "C" void kernel_launch(void* const* d_in, const int* in_sizes, int n_in,
                              void* d_out, int out_size) {
    const float* segin    = (const float*)d_in[0];
    const float* edgein   = (const float*)d_in[1];
    const int*   segmask  = (const int*)  d_in[2];
    const int*   edgemask = (const int*)  d_in[3];

    dim3 grid(NBLK, NN);          // 256 x 8
    k_hist<<<grid, TPB>>>(segmask, edgein, edgemask);
    k_main<<<grid, TPB>>>(segin, (float*)d_out);
}